// round 12
// baseline (speedup 1.0000x reference)
#include <cuda_runtime.h>
#include <math.h>
#include <stdint.h>

#define NB 256
#define S  4096
#define FO 8
#define NM 64
#define FM 6
#define EPSF 1e-5f

#define G    768          // persistent CTAs (6/SM * 148 = 888 capacity -> all resident)
#define PT   256
#define CF   1024         // float4 per chunk (16 KB)
#define PROC_CHUNKS 16384 // 256 instances * 64 chunks
#define PROC_SLOTS  16896 // padded to 22 iterations (768*22)
#define OPES_CHUNKS 2048  // 256 instances * 8 chunks
#define TOTAL_SLOTS 19200 // 25 iterations
#define NITER (TOTAL_SLOTS / G)   // 25
#define BUF4 1120         // 1024 data + 96 mas float4

// -------- device scratch --------
__device__ float4 g_part4[PROC_CHUNKS];          // proc chunk partials (s, ss, cnt, -)
__device__ float  g_opart[OPES_CHUNKS][16];      // opes chunk partials: sum[8], sumsq[8]
__device__ float  g_mean[NB], g_rstd[NB];
__device__ float  g_oM[NB * FO], g_oR[NB * FO];
__device__ unsigned g_pcnt[NB], g_pfin[NB];
__device__ volatile unsigned g_pready[NB];
__device__ unsigned g_ocnt[NB], g_ofin[NB];
__device__ volatile unsigned g_oready[NB];

__device__ __forceinline__ uint32_t smem_u32(const void* p) {
    return (uint32_t)__cvta_generic_to_shared((void*)p);
}
__device__ __forceinline__ void cp16(uint32_t s, const void* g) {
    asm volatile("cp.async.cg.shared.global [%0], [%1], 16;" :: "r"(s), "l"(g));
}

__global__ void __launch_bounds__(PT, 6)
fused_k(const float4* __restrict__ pt, float4* __restrict__ out_proc,
        const float4* __restrict__ opes4, float4* __restrict__ out_opes,
        const float4* __restrict__ mas4, float* __restrict__ out_mas,
        const int* __restrict__ nums) {
    __shared__ float4 buf[2][BUF4];
    __shared__ float  sh[3][8];
    __shared__ float4 shs[8][2], shq[8][2];
    __shared__ float  stat2[2];
    __shared__ float  M[FO], R[FO];
    __shared__ float  mM[2][FM], mR[2][FM];
    __shared__ int    lastflag;

    const int c = blockIdx.x;
    const int t = threadIdx.x;
    const int lane = t & 31, w = t >> 5;
    const uint32_t sb0 = smem_u32(&buf[0][0]);
    const uint32_t sb1 = smem_u32(&buf[1][0]);

    for (int j = 0; j <= NITER; j++) {
        const int cur = j & 1;
        const uint32_t sbc = cur ? sb1 : sb0;

        // ---------- decode current slot ----------
        int type = -1, b = 0, sub = 0;
        size_t gbase = 0;
        if (j < NITER) {
            const int slot = j * G + c;
            if (slot < PROC_CHUNKS) {
                type = 0; b = slot >> 6; sub = slot & 63;
                gbase = (size_t)slot * CF;
            } else if (slot >= PROC_SLOTS && slot < PROC_SLOTS + OPES_CHUNKS) {
                const int oc = slot - PROC_SLOTS;
                type = 1; b = oc >> 3; sub = oc & 7;
                gbase = (size_t)b * 8192 + (size_t)sub * CF;
            }
        }

        // ---------- A: issue async loads for slot j ----------
        if (type == 0) {
            const float4* src = pt + gbase;
#pragma unroll
            for (int k = 0; k < 4; k++) { int i = t + k * 256; cp16(sbc + i * 16, src + i); }
            asm volatile("cp.async.commit_group;");
        } else if (type == 1) {
            const float4* src = opes4 + gbase;
#pragma unroll
            for (int k = 0; k < 4; k++) { int i = t + k * 256; cp16(sbc + i * 16, src + i); }
            if (sub == 0 && t < 96) cp16(sbc + (1024 + t) * 16, mas4 + (size_t)b * 96 + t);
            asm volatile("cp.async.commit_group;");
        }

        // ---------- B: normalize prev chunk from smem (overlaps A's in-flight loads) ----------
        if (j > 0) {
            const int pslot = (j - 1) * G + c;
            int ptype = -1, pb = 0, psub = 0;
            size_t pgbase = 0;
            if (pslot < PROC_CHUNKS) {
                ptype = 0; pb = pslot >> 6;
                pgbase = (size_t)pslot * CF;
            } else if (pslot >= PROC_SLOTS && pslot < PROC_SLOTS + OPES_CHUNKS) {
                const int oc = pslot - PROC_SLOTS;
                ptype = 1; pb = oc >> 3; psub = oc & 7;
                pgbase = (size_t)pb * 8192 + (size_t)psub * CF;
            }
            const float4* bp = buf[cur ^ 1];

            if (ptype == 0) {
                if (t == 0) {
                    while (g_pready[pb] == 0) __nanosleep(64);
                    __threadfence();
                    stat2[0] = g_mean[pb];
                    stat2[1] = g_rstd[pb];
                }
                __syncthreads();
                const float m = stat2[0], r = stat2[1];
                float4* dst = out_proc + pgbase;
#pragma unroll
                for (int k = 0; k < 4; k++) {
                    const int i = t + k * 256;
                    float4 v = bp[i];
                    float4 o;
                    o.x = (v.x != 0.f) ? (v.x - m) * r : 0.f;
                    o.y = (v.y != 0.f) ? (v.y - m) * r : 0.f;
                    o.z = (v.z != 0.f) ? (v.z - m) * r : 0.f;
                    o.w = (v.w != 0.f) ? (v.w - m) * r : 0.f;
                    __stcs(&dst[i], o);
                }
                if (t == 0) {
                    unsigned o = atomicAdd(&g_pfin[pb], 1u);
                    if (o == 63u) { g_pcnt[pb] = 0u; g_pready[pb] = 0u; g_pfin[pb] = 0u; }
                }
                __syncthreads();
            } else if (ptype == 1) {
                if (t == 0) {
                    while (g_oready[pb] == 0) __nanosleep(64);
                    __threadfence();
                }
                __syncthreads();
                if (t < FO) { M[t] = g_oM[pb * FO + t]; R[t] = g_oR[pb * FO + t]; }
                __syncthreads();
                float4* dst = out_opes + pgbase;
#pragma unroll
                for (int k = 0; k < 4; k++) {
                    const int i = t + k * 256;
                    float4 v = bp[i];
                    const int g = (i & 1) * 4;
                    float4 o;
                    o.x = (v.x - M[g + 0]) * R[g + 0];
                    o.y = (v.y - M[g + 1]) * R[g + 1];
                    o.z = (v.z - M[g + 2]) * R[g + 2];
                    o.w = (v.w - M[g + 3]) * R[g + 3];
                    __stcs(&dst[i], o);
                }
                if (psub == 0) {
                    // mas normalize: data + stats both block-local (stats computed in C(j-1))
                    const float* sm_ = (const float*)(bp + 1024);
                    float* mout = out_mas + (size_t)pb * (NM * FM);
                    const int pc = cur ^ 1;
                    { int i = t;       mout[i] = (sm_[i] - mM[pc][i % FM]) * mR[pc][i % FM]; }
                    if (t < NM * FM - 256) {
                        int i = 256 + t; mout[i] = (sm_[i] - mM[pc][i % FM]) * mR[pc][i % FM];
                    }
                }
                if (t == 0) {
                    unsigned o = atomicAdd(&g_ofin[pb], 1u);
                    if (o == 7u) { g_ocnt[pb] = 0u; g_oready[pb] = 0u; g_ofin[pb] = 0u; }
                }
                __syncthreads();   // close reads of bp (incl. mas region) before next-iter A writes
            }
        }

        // ---------- C: complete loads, accumulate, arrive ----------
        if (type >= 0) {
            asm volatile("cp.async.wait_group 0;");
            __syncthreads();
            const float4* bc = buf[cur];

            if (type == 0) {
                float s = 0.f, ss = 0.f, cc = 0.f;
#pragma unroll
                for (int k = 0; k < 4; k++) {
                    const int i = t + k * 256;
                    float4 v = bc[i];
                    s  += (v.x + v.y) + (v.z + v.w);
                    ss += (v.x * v.x + v.y * v.y) + (v.z * v.z + v.w * v.w);
                    cc += (float)((v.x != 0.f) + (v.y != 0.f) + (v.z != 0.f) + (v.w != 0.f));
                }
#pragma unroll
                for (int o = 16; o > 0; o >>= 1) {
                    s  += __shfl_down_sync(0xffffffffu, s, o);
                    ss += __shfl_down_sync(0xffffffffu, ss, o);
                    cc += __shfl_down_sync(0xffffffffu, cc, o);
                }
                if (lane == 0) { sh[0][w] = s; sh[1][w] = ss; sh[2][w] = cc; }
                __syncthreads();
                if (t == 0) {
                    float ts = 0.f, tss = 0.f, tc = 0.f;
#pragma unroll
                    for (int i = 0; i < 8; i++) { ts += sh[0][i]; tss += sh[1][i]; tc += sh[2][i]; }
                    g_part4[j * G + c] = make_float4(ts, tss, tc, 0.f);
                    __threadfence();
                    unsigned old = atomicAdd(&g_pcnt[b], 1u);
                    lastflag = (old == 63u);
                    if (lastflag) __threadfence();
                }
                __syncthreads();
                if (lastflag && t < 32) {
                    // full warp 0 participates (t < 32): shfl with full mask is safe
                    const int cb = b * 64;
                    float4 p0 = g_part4[cb + t];
                    float4 p1 = g_part4[cb + 32 + t];
                    float s2  = p0.x + p1.x;
                    float ss2 = p0.y + p1.y;
                    float c2  = p0.z + p1.z;
#pragma unroll
                    for (int o = 16; o > 0; o >>= 1) {
                        s2  += __shfl_down_sync(0xffffffffu, s2, o);
                        ss2 += __shfl_down_sync(0xffffffffu, ss2, o);
                        c2  += __shfl_down_sync(0xffffffffu, c2, o);
                    }
                    if (t == 0) {
                        float m   = s2 / c2;
                        float var = (ss2 - s2 * s2 / c2) / (c2 - 1.f);
                        g_mean[b] = m;
                        g_rstd[b] = 1.f / (sqrtf(var) + EPSF);
                        __threadfence();
                        g_pready[b] = 1u;
                    }
                }
            } else {
                // opes chunk: masked accumulate (thread parity fixed: even t -> feats 0-3)
                const int n  = nums[b];
                const int r0 = sub * 512;
                float4 s4 = make_float4(0.f, 0.f, 0.f, 0.f);
                float4 q4 = make_float4(0.f, 0.f, 0.f, 0.f);
#pragma unroll
                for (int k = 0; k < 4; k++) {
                    const int i = t + k * 256;
                    float4 v = bc[i];
                    if (r0 + (i >> 1) < n) {
                        s4.x += v.x; s4.y += v.y; s4.z += v.z; s4.w += v.w;
                        q4.x += v.x * v.x; q4.y += v.y * v.y; q4.z += v.z * v.z; q4.w += v.w * v.w;
                    }
                }
#pragma unroll
                for (int o = 2; o < 32; o <<= 1) {
                    s4.x += __shfl_xor_sync(0xffffffffu, s4.x, o);
                    s4.y += __shfl_xor_sync(0xffffffffu, s4.y, o);
                    s4.z += __shfl_xor_sync(0xffffffffu, s4.z, o);
                    s4.w += __shfl_xor_sync(0xffffffffu, s4.w, o);
                    q4.x += __shfl_xor_sync(0xffffffffu, q4.x, o);
                    q4.y += __shfl_xor_sync(0xffffffffu, q4.y, o);
                    q4.z += __shfl_xor_sync(0xffffffffu, q4.z, o);
                    q4.w += __shfl_xor_sync(0xffffffffu, q4.w, o);
                }
                if (lane < 2) { shs[w][lane] = s4; shq[w][lane] = q4; }
                __syncthreads();
                const int oc = j * G + c - PROC_SLOTS;
                if (t < 16) {
                    // full 16 threads converge; shfl_xor over 8-wide groups with offsets 2..8
                    const int p = t & 1, ww = t >> 1;
                    float4 a = shs[ww][p], q = shq[ww][p];
#pragma unroll
                    for (int o = 2; o < 16; o <<= 1) {
                        a.x += __shfl_xor_sync(0x0000ffffu, a.x, o);
                        a.y += __shfl_xor_sync(0x0000ffffu, a.y, o);
                        a.z += __shfl_xor_sync(0x0000ffffu, a.z, o);
                        a.w += __shfl_xor_sync(0x0000ffffu, a.w, o);
                        q.x += __shfl_xor_sync(0x0000ffffu, q.x, o);
                        q.y += __shfl_xor_sync(0x0000ffffu, q.y, o);
                        q.z += __shfl_xor_sync(0x0000ffffu, q.z, o);
                        q.w += __shfl_xor_sync(0x0000ffffu, q.w, o);
                    }
                    if (t < 2) {
                        float* dstp = &g_opart[oc][t * 4];
                        dstp[0] = a.x; dstp[1] = a.y; dstp[2] = a.z; dstp[3] = a.w;
                        float* dstq = &g_opart[oc][8 + t * 4];
                        dstq[0] = q.x; dstq[1] = q.y; dstq[2] = q.z; dstq[3] = q.w;
                    }
                }
                // mas stats for next iteration's B (block-local, from smem)
                if (sub == 0 && t >= 64 && t < 64 + FM) {
                    const int f = t - 64;
                    const float* sm_ = (const float*)(bc + 1024);
                    float ts = 0.f, tq = 0.f;
#pragma unroll
                    for (int r2 = 0; r2 < NM; r2++) { float x = sm_[r2 * FM + f]; ts += x; tq += x * x; }
                    float fm   = (float)NM;
                    float mean = ts / fm;
                    float var  = (tq - ts * ts / fm) / (fm - 1.f);
                    mM[cur][f] = mean;
                    mR[cur][f] = 1.f / (sqrtf(var) + EPSF);
                }
                __syncthreads();   // t<2 partial writes ordered into t0 before release below
                if (t == 0) {
                    __threadfence();                       // release g_opart writes
                    unsigned old = atomicAdd(&g_ocnt[b], 1u);
                    if (old == 7u) {
                        __threadfence();                   // acquire peers' g_opart writes
                        // finalize entirely on t0: 8 features x 8 partials (serial, trivial)
                        const float fn = (float)n;
#pragma unroll
                        for (int f = 0; f < FO; f++) {
                            float ts = 0.f, tq = 0.f;
#pragma unroll
                            for (int s2 = 0; s2 < 8; s2++) {
                                ts += g_opart[b * 8 + s2][f];
                                tq += g_opart[b * 8 + s2][8 + f];
                            }
                            float mean = ts / fn;
                            float var  = (tq - ts * ts / fn) / (fn - 1.f);
                            g_oM[b * FO + f] = mean;
                            g_oR[b * FO + f] = 1.f / (sqrtf(var) + EPSF);
                        }
                        __threadfence();                   // release stats before ready
                        g_oready[b] = 1u;
                    }
                }
                __syncthreads();
            }
        } else if (j < NITER) {
            __syncthreads();   // idle load slot: keep smem-reuse ordering uniform
        }
    }
}

extern "C" void kernel_launch(void* const* d_in, const int* in_sizes, int n_in,
                              void* d_out, int out_size) {
    const float* raw_opes = (const float*)d_in[0];
    const float* raw_mas  = (const float*)d_in[1];
    const float* proc     = (const float*)d_in[2];
    const int*   nums     = (const int*)d_in[3];

    float* out_opes = (float*)d_out;
    float* out_mas  = out_opes + (size_t)NB * S * FO;
    float* out_proc = out_mas  + (size_t)NB * NM * FM;

    fused_k<<<G, PT>>>((const float4*)proc, (float4*)out_proc,
                       (const float4*)raw_opes, (float4*)out_opes,
                       (const float4*)raw_mas, out_mas, nums);
}

// round 13
// speedup vs baseline: 1.2368x; 1.2368x over previous
#include <cuda_runtime.h>
#include <math.h>
#include <stdint.h>

#define NB 256
#define S  4096
#define FO 8
#define NM 64
#define FM 6
#define EPSF 1e-5f

#define CF   1024            // float4 per chunk (16 KB)
#define PROC_CHUNKS 16384    // 256 inst * 64 chunks
#define NCH  18432           // + 2048 opes chunks
#define HALF 9216            // blocks; chunk A = k, chunk B = HALF + k
#define PT   256

// -------- device scratch (fixed slots; flags self-reset via consumer counts) --------
__device__ float4 g_part4[PROC_CHUNKS];       // proc chunk partials (s, ss, cnt, -)
__device__ float  g_opart[2048][16];          // opes chunk partials: sum[8], sumsq[8]
__device__ float  g_mean[NB], g_rstd[NB];
__device__ float  g_oM[NB * FO], g_oR[NB * FO];
__device__ unsigned g_pcnt[NB], g_pfin[NB];
__device__ volatile unsigned g_pready[NB];
__device__ unsigned g_ocnt[NB], g_ofin[NB];
__device__ volatile unsigned g_oready[NB];

__device__ __forceinline__ uint32_t smem_u32(const void* p) {
    return (uint32_t)__cvta_generic_to_shared((void*)p);
}
__device__ __forceinline__ void cp16(uint32_t s, const void* g) {
    asm volatile("cp.async.cg.shared.global [%0], [%1], 16;" :: "r"(s), "l"(g));
}

__global__ void __launch_bounds__(PT, 6)
fused_k(const float4* __restrict__ pt, float4* __restrict__ out_proc,
        const float4* __restrict__ opes4, float4* __restrict__ out_opes,
        const float4* __restrict__ mas4, float* __restrict__ out_mas,
        const int* __restrict__ nums) {
    __shared__ float4 bufA[CF];
    __shared__ float4 bufB[CF + 96];           // + mas region for opes sub0
    __shared__ float  sh[3][8];
    __shared__ float4 shs[8][2], shq[8][2];
    __shared__ float  stat2[2], M[FO], R[FO], mM[FM], mR[FM];
    __shared__ int    lastA, lastB;

    const int k = blockIdx.x;
    const int t = threadIdx.x;
    const int lane = t & 31, w = t >> 5;

    // ---- decode chunk A (always proc) ----
    const int chA = k;
    const int ba  = chA >> 6;
    const size_t gA = (size_t)chA * CF;

    // ---- decode chunk B ----
    const int chB = HALF + k;
    const int b_is_proc = (chB < PROC_CHUNKS);
    int bb, bsub;
    size_t gB;
    if (b_is_proc) {
        bb = chB >> 6; bsub = chB & 63;
        gB = (size_t)chB * CF;
    } else {
        const int oc = chB - PROC_CHUNKS;
        bb = oc >> 3; bsub = oc & 7;
        gB = (size_t)bb * 8192 + (size_t)bsub * CF;
    }

    // ================= issue both loads up-front =================
    {
        const uint32_t sA = smem_u32(bufA);
        const float4* src = pt + gA;
#pragma unroll
        for (int q = 0; q < 4; q++) { int i = t + q * 256; cp16(sA + i * 16, src + i); }
        asm volatile("cp.async.commit_group;");

        const uint32_t sB = smem_u32(bufB);
        const float4* srcB = b_is_proc ? (pt + gB) : (opes4 + gB);
#pragma unroll
        for (int q = 0; q < 4; q++) { int i = t + q * 256; cp16(sB + i * 16, srcB + i); }
        if (!b_is_proc && bsub == 0 && t < 96)
            cp16(sB + (CF + t) * 16, mas4 + (size_t)bb * 96 + t);
        asm volatile("cp.async.commit_group;");
    }

    // ================= stats A (proc) =================
    asm volatile("cp.async.wait_group 1;");
    __syncthreads();
    {
        float s = 0.f, ss = 0.f, cc = 0.f;
#pragma unroll
        for (int q = 0; q < 4; q++) {
            const int i = t + q * 256;
            float4 v = bufA[i];
            s  += (v.x + v.y) + (v.z + v.w);
            ss += (v.x * v.x + v.y * v.y) + (v.z * v.z + v.w * v.w);
            cc += (float)((v.x != 0.f) + (v.y != 0.f) + (v.z != 0.f) + (v.w != 0.f));
        }
#pragma unroll
        for (int o = 16; o > 0; o >>= 1) {
            s  += __shfl_down_sync(0xffffffffu, s, o);
            ss += __shfl_down_sync(0xffffffffu, ss, o);
            cc += __shfl_down_sync(0xffffffffu, cc, o);
        }
        if (lane == 0) { sh[0][w] = s; sh[1][w] = ss; sh[2][w] = cc; }
        __syncthreads();
        if (t == 0) {
            float ts = 0.f, tss = 0.f, tc = 0.f;
#pragma unroll
            for (int i = 0; i < 8; i++) { ts += sh[0][i]; tss += sh[1][i]; tc += sh[2][i]; }
            g_part4[chA] = make_float4(ts, tss, tc, 0.f);
            __threadfence();
            unsigned old = atomicAdd(&g_pcnt[ba], 1u);
            lastA = (old == 63u);
            if (lastA) __threadfence();
        }
        __syncthreads();
        if (lastA && t < 32) {
            const int cb = ba * 64;
            float4 p0 = g_part4[cb + t];
            float4 p1 = g_part4[cb + 32 + t];
            float s2 = p0.x + p1.x, ss2 = p0.y + p1.y, c2 = p0.z + p1.z;
#pragma unroll
            for (int o = 16; o > 0; o >>= 1) {
                s2  += __shfl_down_sync(0xffffffffu, s2, o);
                ss2 += __shfl_down_sync(0xffffffffu, ss2, o);
                c2  += __shfl_down_sync(0xffffffffu, c2, o);
            }
            if (t == 0) {
                float m   = s2 / c2;
                float var = (ss2 - s2 * s2 / c2) / (c2 - 1.f);
                g_mean[ba] = m;
                g_rstd[ba] = 1.f / (sqrtf(var) + EPSF);
                __threadfence();
                g_pready[ba] = 1u;
            }
        }
    }

    // ================= stats B =================
    asm volatile("cp.async.wait_group 0;");
    __syncthreads();
    if (b_is_proc) {
        float s = 0.f, ss = 0.f, cc = 0.f;
#pragma unroll
        for (int q = 0; q < 4; q++) {
            const int i = t + q * 256;
            float4 v = bufB[i];
            s  += (v.x + v.y) + (v.z + v.w);
            ss += (v.x * v.x + v.y * v.y) + (v.z * v.z + v.w * v.w);
            cc += (float)((v.x != 0.f) + (v.y != 0.f) + (v.z != 0.f) + (v.w != 0.f));
        }
#pragma unroll
        for (int o = 16; o > 0; o >>= 1) {
            s  += __shfl_down_sync(0xffffffffu, s, o);
            ss += __shfl_down_sync(0xffffffffu, ss, o);
            cc += __shfl_down_sync(0xffffffffu, cc, o);
        }
        if (lane == 0) { sh[0][w] = s; sh[1][w] = ss; sh[2][w] = cc; }
        __syncthreads();
        if (t == 0) {
            float ts = 0.f, tss = 0.f, tc = 0.f;
#pragma unroll
            for (int i = 0; i < 8; i++) { ts += sh[0][i]; tss += sh[1][i]; tc += sh[2][i]; }
            g_part4[chB] = make_float4(ts, tss, tc, 0.f);
            __threadfence();
            unsigned old = atomicAdd(&g_pcnt[bb], 1u);
            lastB = (old == 63u);
            if (lastB) __threadfence();
        }
        __syncthreads();
        if (lastB && t < 32) {
            const int cb = bb * 64;
            float4 p0 = g_part4[cb + t];
            float4 p1 = g_part4[cb + 32 + t];
            float s2 = p0.x + p1.x, ss2 = p0.y + p1.y, c2 = p0.z + p1.z;
#pragma unroll
            for (int o = 16; o > 0; o >>= 1) {
                s2  += __shfl_down_sync(0xffffffffu, s2, o);
                ss2 += __shfl_down_sync(0xffffffffu, ss2, o);
                c2  += __shfl_down_sync(0xffffffffu, c2, o);
            }
            if (t == 0) {
                float m   = s2 / c2;
                float var = (ss2 - s2 * s2 / c2) / (c2 - 1.f);
                g_mean[bb] = m;
                g_rstd[bb] = 1.f / (sqrtf(var) + EPSF);
                __threadfence();
                g_pready[bb] = 1u;
            }
        }
    } else {
        const int n  = nums[bb];
        const int r0 = bsub * 512;
        float4 s4 = make_float4(0.f, 0.f, 0.f, 0.f);
        float4 q4 = make_float4(0.f, 0.f, 0.f, 0.f);
#pragma unroll
        for (int q = 0; q < 4; q++) {
            const int i = t + q * 256;
            float4 v = bufB[i];
            if (r0 + (i >> 1) < n) {
                s4.x += v.x; s4.y += v.y; s4.z += v.z; s4.w += v.w;
                q4.x += v.x * v.x; q4.y += v.y * v.y; q4.z += v.z * v.z; q4.w += v.w * v.w;
            }
        }
#pragma unroll
        for (int o = 2; o < 32; o <<= 1) {
            s4.x += __shfl_xor_sync(0xffffffffu, s4.x, o);
            s4.y += __shfl_xor_sync(0xffffffffu, s4.y, o);
            s4.z += __shfl_xor_sync(0xffffffffu, s4.z, o);
            s4.w += __shfl_xor_sync(0xffffffffu, s4.w, o);
            q4.x += __shfl_xor_sync(0xffffffffu, q4.x, o);
            q4.y += __shfl_xor_sync(0xffffffffu, q4.y, o);
            q4.z += __shfl_xor_sync(0xffffffffu, q4.z, o);
            q4.w += __shfl_xor_sync(0xffffffffu, q4.w, o);
        }
        if (lane < 2) { shs[w][lane] = s4; shq[w][lane] = q4; }
        // mas stats (sub0): block-local from bufB tail
        if (bsub == 0 && t >= 64 && t < 64 + FM) {
            const int f = t - 64;
            const float* sm_ = (const float*)(bufB + CF);
            float ts = 0.f, tq = 0.f;
#pragma unroll
            for (int r2 = 0; r2 < NM; r2++) { float x = sm_[r2 * FM + f]; ts += x; tq += x * x; }
            float fm   = (float)NM;
            float mean = ts / fm;
            float var  = (tq - ts * ts / fm) / (fm - 1.f);
            mM[f] = mean;
            mR[f] = 1.f / (sqrtf(var) + EPSF);
        }
        __syncthreads();
        const int oc = chB - PROC_CHUNKS;
        if (t < 16) {
            const int p = t & 1, ww = t >> 1;
            float4 a = shs[ww][p], q = shq[ww][p];
#pragma unroll
            for (int o = 2; o < 16; o <<= 1) {
                a.x += __shfl_xor_sync(0x0000ffffu, a.x, o);
                a.y += __shfl_xor_sync(0x0000ffffu, a.y, o);
                a.z += __shfl_xor_sync(0x0000ffffu, a.z, o);
                a.w += __shfl_xor_sync(0x0000ffffu, a.w, o);
                q.x += __shfl_xor_sync(0x0000ffffu, q.x, o);
                q.y += __shfl_xor_sync(0x0000ffffu, q.y, o);
                q.z += __shfl_xor_sync(0x0000ffffu, q.z, o);
                q.w += __shfl_xor_sync(0x0000ffffu, q.w, o);
            }
            if (t < 2) {
                float* dp = &g_opart[oc][t * 4];
                dp[0] = a.x; dp[1] = a.y; dp[2] = a.z; dp[3] = a.w;
                float* dq = &g_opart[oc][8 + t * 4];
                dq[0] = q.x; dq[1] = q.y; dq[2] = q.z; dq[3] = q.w;
            }
        }
        __syncthreads();   // t<2 writes ordered into t0
        if (t == 0) {
            __threadfence();
            unsigned old = atomicAdd(&g_ocnt[bb], 1u);
            if (old == 7u) {
                __threadfence();
                const float fn = (float)n;
#pragma unroll
                for (int f = 0; f < FO; f++) {
                    float ts = 0.f, tq = 0.f;
#pragma unroll
                    for (int s2 = 0; s2 < 8; s2++) {
                        ts += g_opart[bb * 8 + s2][f];
                        tq += g_opart[bb * 8 + s2][8 + f];
                    }
                    float mean = ts / fn;
                    float var  = (tq - ts * ts / fn) / (fn - 1.f);
                    g_oM[bb * FO + f] = mean;
                    g_oR[bb * FO + f] = 1.f / (sqrtf(var) + EPSF);
                }
                __threadfence();
                g_oready[bb] = 1u;
            }
        }
    }

    // ================= norm A (proc) =================
    {
        if (t == 0) {
            while (g_pready[ba] == 0) __nanosleep(64);
            __threadfence();
            stat2[0] = g_mean[ba];
            stat2[1] = g_rstd[ba];
        }
        __syncthreads();
        const float m = stat2[0], r = stat2[1];
        float4* dst = out_proc + gA;
#pragma unroll
        for (int q = 0; q < 4; q++) {
            const int i = t + q * 256;
            float4 v = bufA[i];
            float4 o;
            o.x = (v.x != 0.f) ? (v.x - m) * r : 0.f;
            o.y = (v.y != 0.f) ? (v.y - m) * r : 0.f;
            o.z = (v.z != 0.f) ? (v.z - m) * r : 0.f;
            o.w = (v.w != 0.f) ? (v.w - m) * r : 0.f;
            __stcs(&dst[i], o);
        }
        if (t == 0) {
            unsigned o = atomicAdd(&g_pfin[ba], 1u);
            if (o == 63u) { g_pcnt[ba] = 0u; g_pready[ba] = 0u; g_pfin[ba] = 0u; }
        }
    }

    // ================= norm B =================
    if (b_is_proc) {
        __syncthreads();   // stat2 reuse
        if (t == 0) {
            while (g_pready[bb] == 0) __nanosleep(64);
            __threadfence();
            stat2[0] = g_mean[bb];
            stat2[1] = g_rstd[bb];
        }
        __syncthreads();
        const float m = stat2[0], r = stat2[1];
        float4* dst = out_proc + gB;
#pragma unroll
        for (int q = 0; q < 4; q++) {
            const int i = t + q * 256;
            float4 v = bufB[i];
            float4 o;
            o.x = (v.x != 0.f) ? (v.x - m) * r : 0.f;
            o.y = (v.y != 0.f) ? (v.y - m) * r : 0.f;
            o.z = (v.z != 0.f) ? (v.z - m) * r : 0.f;
            o.w = (v.w != 0.f) ? (v.w - m) * r : 0.f;
            __stcs(&dst[i], o);
        }
        if (t == 0) {
            unsigned o = atomicAdd(&g_pfin[bb], 1u);
            if (o == 63u) { g_pcnt[bb] = 0u; g_pready[bb] = 0u; g_pfin[bb] = 0u; }
        }
    } else {
        if (t == 0) {
            while (g_oready[bb] == 0) __nanosleep(64);
            __threadfence();
        }
        __syncthreads();
        if (t < FO) { M[t] = g_oM[bb * FO + t]; R[t] = g_oR[bb * FO + t]; }
        __syncthreads();
        float4* dst = out_opes + gB;
#pragma unroll
        for (int q = 0; q < 4; q++) {
            const int i = t + q * 256;
            float4 v = bufB[i];
            const int g = (i & 1) * 4;
            float4 o;
            o.x = (v.x - M[g + 0]) * R[g + 0];
            o.y = (v.y - M[g + 1]) * R[g + 1];
            o.z = (v.z - M[g + 2]) * R[g + 2];
            o.w = (v.w - M[g + 3]) * R[g + 3];
            __stcs(&dst[i], o);
        }
        if (bsub == 0) {
            const float* sm_ = (const float*)(bufB + CF);
            float* mout = out_mas + (size_t)bb * (NM * FM);
            { int i = t;       mout[i] = (sm_[i] - mM[i % FM]) * mR[i % FM]; }
            if (t < NM * FM - 256) {
                int i = 256 + t; mout[i] = (sm_[i] - mM[i % FM]) * mR[i % FM];
            }
        }
        if (t == 0) {
            unsigned o = atomicAdd(&g_ofin[bb], 1u);
            if (o == 7u) { g_ocnt[bb] = 0u; g_oready[bb] = 0u; g_ofin[bb] = 0u; }
        }
    }
}

extern "C" void kernel_launch(void* const* d_in, const int* in_sizes, int n_in,
                              void* d_out, int out_size) {
    const float* raw_opes = (const float*)d_in[0];
    const float* raw_mas  = (const float*)d_in[1];
    const float* proc     = (const float*)d_in[2];
    const int*   nums     = (const int*)d_in[3];

    float* out_opes = (float*)d_out;
    float* out_mas  = out_opes + (size_t)NB * S * FO;
    float* out_proc = out_mas  + (size_t)NB * NM * FM;

    fused_k<<<HALF, PT>>>((const float4*)proc, (float4*)out_proc,
                          (const float4*)raw_opes, (float4*)out_opes,
                          (const float4*)raw_mas, out_mas, nums);
}

// round 14
// speedup vs baseline: 1.4763x; 1.1936x over previous
#include <cuda_runtime.h>
#include <math.h>

#define NB 256
#define S  4096
#define FO 8
#define NM 64
#define FM 6
#define EPSF 1e-5f

#define PBLK 16     // proc stats sub-blocks per instance
#define OSB  4      // opes stats sub-blocks per instance
#define NPB  32     // proc norm sub-blocks per instance
#define OPB  8      // opes norm sub-blocks per instance
#define NSTAT (PBLK + OSB)     // 20
#define NNORM (NPB + OPB)      // 40
#define LEAD  64               // norm(b) dispatched alongside stats(b+LEAD); HEAD > wave-1 residency
#define GRID_T (NB * (NSTAT + NNORM))   // 15360

// -------- device scratch (fixed slots; flags self-reset each replay) --------
__device__ float g_part[NB][PBLK][4];
__device__ float g_opart[NB][OSB][2][FO];
__device__ float g_mmean[NB * FM];
__device__ float g_mrstd[NB * FM];
__device__ unsigned g_cnt[NB],  g_fin[NB];
__device__ unsigned g_ocnt[NB], g_ofin[NB];

__device__ __forceinline__ float warp_sum(float v) {
#pragma unroll
    for (int o = 16; o > 0; o >>= 1) v += __shfl_down_sync(0xffffffffu, v, o);
    return v;
}

__device__ __forceinline__ void wait_for(unsigned* cnt, unsigned target) {
    if (threadIdx.x == 0) {
        volatile unsigned* p = (volatile unsigned*)cnt;
        while (*p < target) __nanosleep(32);
        __threadfence();
    }
    __syncthreads();
}

__device__ __forceinline__ void retire(unsigned* fin, unsigned* cnt, unsigned nCons) {
    if (threadIdx.x == 0) {
        unsigned o = atomicAdd(fin, 1u);
        if (o == nCons - 1) { *cnt = 0u; *fin = 0u; }
    }
}

// ---------------- role bodies ----------------
__device__ void proc_stats(const float4* __restrict__ pt, int b, int sub) {
    const float4* src = pt + (size_t)b * (S * NM / 4) + (size_t)sub * 4096;
    float s = 0.f, ss = 0.f, c = 0.f;
    for (int i0 = threadIdx.x; i0 < 4096; i0 += 1024) {
        float4 v[4];
#pragma unroll
        for (int k = 0; k < 4; k++) v[k] = src[i0 + k * 256];   // cached: prime L2 for norm
#pragma unroll
        for (int k = 0; k < 4; k++) {
            s  += (v[k].x + v[k].y) + (v[k].z + v[k].w);
            ss += (v[k].x * v[k].x + v[k].y * v[k].y) + (v[k].z * v[k].z + v[k].w * v[k].w);
            c  += (float)((v[k].x != 0.f) + (v[k].y != 0.f) + (v[k].z != 0.f) + (v[k].w != 0.f));
        }
    }
    __shared__ float sh[3][8];
    int lane = threadIdx.x & 31, w = threadIdx.x >> 5;
    s = warp_sum(s); ss = warp_sum(ss); c = warp_sum(c);
    if (lane == 0) { sh[0][w] = s; sh[1][w] = ss; sh[2][w] = c; }
    __syncthreads();
    if (threadIdx.x == 0) {
        float ts = 0.f, tss = 0.f, tc = 0.f;
#pragma unroll
        for (int i = 0; i < 8; i++) { ts += sh[0][i]; tss += sh[1][i]; tc += sh[2][i]; }
        g_part[b][sub][0] = ts;
        g_part[b][sub][1] = tss;
        g_part[b][sub][2] = tc;
        __threadfence();
        atomicAdd(&g_cnt[b], 1u);
    }
}

__device__ void opes_stats(const float* __restrict__ opes, const float* __restrict__ mas,
                           const int* __restrict__ nums, int b, int sub) {
    const int n  = nums[b];
    const int r0 = sub * 1024;
    const int r1 = min(r0 + 1024, n);

    float s[FO], q[FO];
#pragma unroll
    for (int f = 0; f < FO; f++) { s[f] = 0.f; q[f] = 0.f; }

    const float4* op = (const float4*)(opes + (size_t)b * S * FO);
    for (int r = r0 + threadIdx.x; r < r1; r += 256) {
        float4 a  = op[r * 2];          // cached: prime L2 for norm
        float4 b4 = op[r * 2 + 1];
        float x[FO] = {a.x, a.y, a.z, a.w, b4.x, b4.y, b4.z, b4.w};
#pragma unroll
        for (int f = 0; f < FO; f++) { s[f] += x[f]; q[f] += x[f] * x[f]; }
    }
    __shared__ float sh[16][8];
    int lane = threadIdx.x & 31, w = threadIdx.x >> 5;
#pragma unroll
    for (int f = 0; f < FO; f++) {
        float rs = warp_sum(s[f]);
        float rq = warp_sum(q[f]);
        if (lane == 0) { sh[f][w] = rs; sh[f + 8][w] = rq; }
    }
    __syncthreads();
    if (threadIdx.x < FO) {
        int f = threadIdx.x;
        float ts = 0.f, tq = 0.f;
#pragma unroll
        for (int i = 0; i < 8; i++) { ts += sh[f][i]; tq += sh[f + 8][i]; }
        g_opart[b][sub][0][f] = ts;
        g_opart[b][sub][1][f] = tq;
    }
    if (sub == 0 && threadIdx.x >= 64 && threadIdx.x < 64 + FM) {
        int f = threadIdx.x - 64;
        const float* mp = mas + (size_t)b * NM * FM + f;
        float ts = 0.f, tq = 0.f;
#pragma unroll
        for (int m = 0; m < NM; m++) { float x = mp[m * FM]; ts += x; tq += x * x; }
        float fm   = (float)NM;
        float mean = ts / fm;
        float var  = (tq - ts * ts / fm) / (fm - 1.f);
        g_mmean[b * FM + f] = mean;
        g_mrstd[b * FM + f] = 1.f / (sqrtf(var) + EPSF);
    }
    __syncthreads();
    if (threadIdx.x == 0) { __threadfence(); atomicAdd(&g_ocnt[b], 1u); }
}

__device__ void proc_norm(const float4* __restrict__ pt, float4* __restrict__ out_proc,
                          int b, int sub) {
    wait_for(&g_cnt[b], PBLK);

    __shared__ float sm, sr;
    if (threadIdx.x < 32) {
        int lane = threadIdx.x;
        float s = 0.f, ss = 0.f, c = 0.f;
        if (lane < PBLK) {
            s  = g_part[b][lane][0];
            ss = g_part[b][lane][1];
            c  = g_part[b][lane][2];
        }
#pragma unroll
        for (int o = 8; o > 0; o >>= 1) {
            s  += __shfl_down_sync(0xffffffffu, s, o);
            ss += __shfl_down_sync(0xffffffffu, ss, o);
            c  += __shfl_down_sync(0xffffffffu, c, o);
        }
        if (lane == 0) {
            float m   = s / c;
            float var = (ss - s * s / c) / (c - 1.f);
            sm = m;
            sr = 1.f / (sqrtf(var) + EPSF);
        }
    }
    __syncthreads();
    retire(&g_fin[b], &g_cnt[b], NPB);
    const float m = sm, r = sr;

    const size_t base = (size_t)b * (S * NM / 4) + (size_t)sub * 2048;
    const float4* src = pt + base;
    float4*       dst = out_proc + base;
    for (int i0 = threadIdx.x; i0 < 2048; i0 += 512) {
        float4 v0 = __ldcs(&src[i0]);
        float4 v1 = __ldcs(&src[i0 + 256]);
        float4 o0, o1;
        o0.x = (v0.x != 0.f) ? (v0.x - m) * r : 0.f;
        o0.y = (v0.y != 0.f) ? (v0.y - m) * r : 0.f;
        o0.z = (v0.z != 0.f) ? (v0.z - m) * r : 0.f;
        o0.w = (v0.w != 0.f) ? (v0.w - m) * r : 0.f;
        o1.x = (v1.x != 0.f) ? (v1.x - m) * r : 0.f;
        o1.y = (v1.y != 0.f) ? (v1.y - m) * r : 0.f;
        o1.z = (v1.z != 0.f) ? (v1.z - m) * r : 0.f;
        o1.w = (v1.w != 0.f) ? (v1.w - m) * r : 0.f;
        __stcs(&dst[i0], o0);
        __stcs(&dst[i0 + 256], o1);
    }
}

__device__ void opes_norm(const float* __restrict__ opes, float4* __restrict__ out_opes,
                          const float* __restrict__ mas, float* __restrict__ out_mas,
                          const int* __restrict__ nums, int b, int sub) {
    const int base = b * 8192 + sub * 1024;

    wait_for(&g_ocnt[b], OSB);

    __shared__ float mm[FO], rr[FO];
    if (threadIdx.x < FO) {
        const int f = threadIdx.x;
        float ts = 0.f, tq = 0.f;
#pragma unroll
        for (int s2 = 0; s2 < OSB; s2++) {
            ts += g_opart[b][s2][0][f];
            tq += g_opart[b][s2][1][f];
        }
        float fn   = (float)nums[b];
        float mean = ts / fn;
        float var  = (tq - ts * ts / fn) / (fn - 1.f);
        mm[f] = mean;
        rr[f] = 1.f / (sqrtf(var) + EPSF);
    }
    __syncthreads();
    retire(&g_ofin[b], &g_ocnt[b], OPB);

    const float4* src = (const float4*)opes;
    for (int i0 = threadIdx.x; i0 < 1024; i0 += 512) {
        float4 v0 = __ldcs(&src[base + i0]);
        float4 v1 = __ldcs(&src[base + i0 + 256]);
        const float* M0 = &mm[(i0 & 1) * 4];
        const float* R0 = &rr[(i0 & 1) * 4];
        const float* M1 = &mm[((i0 + 256) & 1) * 4];
        const float* R1 = &rr[((i0 + 256) & 1) * 4];
        float4 o0, o1;
        o0.x = (v0.x - M0[0]) * R0[0];
        o0.y = (v0.y - M0[1]) * R0[1];
        o0.z = (v0.z - M0[2]) * R0[2];
        o0.w = (v0.w - M0[3]) * R0[3];
        o1.x = (v1.x - M1[0]) * R1[0];
        o1.y = (v1.y - M1[1]) * R1[1];
        o1.z = (v1.z - M1[2]) * R1[2];
        o1.w = (v1.w - M1[3]) * R1[3];
        __stcs(&out_opes[base + i0], o0);
        __stcs(&out_opes[base + i0 + 256], o1);
    }

    if (sub == 0) {
        const float* min_ = mas + (size_t)b * NM * FM;
        float*       mout = out_mas + (size_t)b * NM * FM;
        for (int i = threadIdx.x; i < NM * FM; i += 256) {
            int f = i % FM;
            mout[i] = (min_[i] - g_mmean[b * FM + f]) * g_mrstd[b * FM + f];
        }
    }
}

// ---------------- interleaved dispatch ----------------
// bid layout:
//   [0, LEAD*NSTAT)                      : stats(b=0..LEAD-1)       (HEAD=1280 > wave-1)
//   [.., +(NB-LEAD)*(NSTAT+NNORM))       : per b: stats(b), norm(b-LEAD)
//   tail                                 : norm(b=NB-LEAD..NB-1)
__global__ void __launch_bounds__(256)
fusedAB_k(const float4* __restrict__ pt, float4* __restrict__ out_proc,
          const float* __restrict__ opes, float4* __restrict__ out_opes,
          const float* __restrict__ mas, float* __restrict__ out_mas,
          const int* __restrict__ nums) {
    const int bid = blockIdx.x;
    const int HEAD = LEAD * NSTAT;                              // 1280
    const int MID  = HEAD + (NB - LEAD) * (NSTAT + NNORM);      // 1280 + 11520 = 12800

    int b, sub, is_stats;
    if (bid < HEAD) {
        b = bid / NSTAT; sub = bid % NSTAT; is_stats = 1;
    } else if (bid < MID) {
        int t = bid - HEAD;
        int seg = t / (NSTAT + NNORM);
        int k   = t % (NSTAT + NNORM);
        if (k < NSTAT) { b = LEAD + seg; sub = k; is_stats = 1; }
        else           { b = seg;        sub = k - NSTAT; is_stats = 0; }
    } else {
        int t = bid - MID;
        b = (NB - LEAD) + t / NNORM; sub = t % NNORM; is_stats = 0;
    }

    if (is_stats) {
        if (sub < PBLK) proc_stats(pt, b, sub);
        else            opes_stats(opes, mas, nums, b, sub - PBLK);
    } else {
        if (sub < NPB)  proc_norm(pt, out_proc, b, sub);
        else            opes_norm(opes, out_opes, mas, out_mas, nums, b, sub - NPB);
    }
}

extern "C" void kernel_launch(void* const* d_in, const int* in_sizes, int n_in,
                              void* d_out, int out_size) {
    const float* raw_opes = (const float*)d_in[0];
    const float* raw_mas  = (const float*)d_in[1];
    const float* proc     = (const float*)d_in[2];
    const int*   nums     = (const int*)d_in[3];

    float* out_opes = (float*)d_out;
    float* out_mas  = out_opes + (size_t)NB * S * FO;
    float* out_proc = out_mas  + (size_t)NB * NM * FM;

    fusedAB_k<<<GRID_T, 256>>>((const float4*)proc, (float4*)out_proc,
                               raw_opes, (float4*)out_opes,
                               raw_mas, out_mas, nums);
}

// round 15
// speedup vs baseline: 1.7076x; 1.1567x over previous
#include <cuda_runtime.h>
#include <math.h>

#define NB 256
#define S  4096
#define FO 8
#define NM 64
#define FM 6
#define EPSF 1e-5f

#define PBLK 16     // proc stats sub-blocks per instance
#define OSB  4      // opes stats sub-blocks per instance
#define NPB  32     // proc norm sub-blocks per instance
#define OPB  8      // opes norm sub-blocks per instance
#define NSTAT (PBLK + OSB)     // 20
#define NNORM (NPB + OPB)      // 40
#define LEAD  32               // reuse window ~32MB (L2-safe) and head > most of wave-1
#define GRID_T (NB * (NSTAT + NNORM))   // 15360

// -------- device scratch (fixed slots; flags self-reset each replay) --------
__device__ float g_part[NB][PBLK][4];
__device__ float g_opart[NB][OSB][2][FO];
__device__ float g_mmean[NB * FM];
__device__ float g_mrstd[NB * FM];
__device__ unsigned g_cnt[NB],  g_fin[NB];
__device__ unsigned g_ocnt[NB], g_ofin[NB];

__device__ __forceinline__ float warp_sum(float v) {
#pragma unroll
    for (int o = 16; o > 0; o >>= 1) v += __shfl_down_sync(0xffffffffu, v, o);
    return v;
}

__device__ __forceinline__ void wait_for(unsigned* cnt, unsigned target) {
    if (threadIdx.x == 0) {
        volatile unsigned* p = (volatile unsigned*)cnt;
        while (*p < target) __nanosleep(32);
        __threadfence();
    }
    __syncthreads();
}

__device__ __forceinline__ void retire(unsigned* fin, unsigned* cnt, unsigned nCons) {
    if (threadIdx.x == 0) {
        unsigned o = atomicAdd(fin, 1u);
        if (o == nCons - 1) { *cnt = 0u; *fin = 0u; }
    }
}

// ---------------- role bodies ----------------
__device__ void proc_stats(const float4* __restrict__ pt, int b, int sub) {
    const float4* src = pt + (size_t)b * (S * NM / 4) + (size_t)sub * 4096;
    float s = 0.f, ss = 0.f, c = 0.f;
    for (int i0 = threadIdx.x; i0 < 4096; i0 += 1024) {
        float4 v[4];
#pragma unroll
        for (int k = 0; k < 4; k++) v[k] = src[i0 + k * 256];   // cached: prime L2 for norm
#pragma unroll
        for (int k = 0; k < 4; k++) {
            s  += (v[k].x + v[k].y) + (v[k].z + v[k].w);
            ss += (v[k].x * v[k].x + v[k].y * v[k].y) + (v[k].z * v[k].z + v[k].w * v[k].w);
            c  += (float)((v[k].x != 0.f) + (v[k].y != 0.f) + (v[k].z != 0.f) + (v[k].w != 0.f));
        }
    }
    __shared__ float sh[3][8];
    int lane = threadIdx.x & 31, w = threadIdx.x >> 5;
    s = warp_sum(s); ss = warp_sum(ss); c = warp_sum(c);
    if (lane == 0) { sh[0][w] = s; sh[1][w] = ss; sh[2][w] = c; }
    __syncthreads();
    if (threadIdx.x == 0) {
        float ts = 0.f, tss = 0.f, tc = 0.f;
#pragma unroll
        for (int i = 0; i < 8; i++) { ts += sh[0][i]; tss += sh[1][i]; tc += sh[2][i]; }
        g_part[b][sub][0] = ts;
        g_part[b][sub][1] = tss;
        g_part[b][sub][2] = tc;
        __threadfence();
        atomicAdd(&g_cnt[b], 1u);
    }
}

__device__ void opes_stats(const float* __restrict__ opes, const float* __restrict__ mas,
                           const int* __restrict__ nums, int b, int sub) {
    const int n  = nums[b];
    const int r0 = sub * 1024;
    const int r1 = min(r0 + 1024, n);

    float s[FO], q[FO];
#pragma unroll
    for (int f = 0; f < FO; f++) { s[f] = 0.f; q[f] = 0.f; }

    const float4* op = (const float4*)(opes + (size_t)b * S * FO);
    for (int r = r0 + threadIdx.x; r < r1; r += 256) {
        float4 a  = op[r * 2];          // cached: prime L2 for norm
        float4 b4 = op[r * 2 + 1];
        float x[FO] = {a.x, a.y, a.z, a.w, b4.x, b4.y, b4.z, b4.w};
#pragma unroll
        for (int f = 0; f < FO; f++) { s[f] += x[f]; q[f] += x[f] * x[f]; }
    }
    __shared__ float sh[16][8];
    int lane = threadIdx.x & 31, w = threadIdx.x >> 5;
#pragma unroll
    for (int f = 0; f < FO; f++) {
        float rs = warp_sum(s[f]);
        float rq = warp_sum(q[f]);
        if (lane == 0) { sh[f][w] = rs; sh[f + 8][w] = rq; }
    }
    __syncthreads();
    if (threadIdx.x < FO) {
        int f = threadIdx.x;
        float ts = 0.f, tq = 0.f;
#pragma unroll
        for (int i = 0; i < 8; i++) { ts += sh[f][i]; tq += sh[f + 8][i]; }
        g_opart[b][sub][0][f] = ts;
        g_opart[b][sub][1][f] = tq;
    }
    if (sub == 0 && threadIdx.x >= 64 && threadIdx.x < 64 + FM) {
        int f = threadIdx.x - 64;
        const float* mp = mas + (size_t)b * NM * FM + f;
        float ts = 0.f, tq = 0.f;
#pragma unroll
        for (int m = 0; m < NM; m++) { float x = mp[m * FM]; ts += x; tq += x * x; }
        float fm   = (float)NM;
        float mean = ts / fm;
        float var  = (tq - ts * ts / fm) / (fm - 1.f);
        g_mmean[b * FM + f] = mean;
        g_mrstd[b * FM + f] = 1.f / (sqrtf(var) + EPSF);
    }
    __syncthreads();
    if (threadIdx.x == 0) { __threadfence(); atomicAdd(&g_ocnt[b], 1u); }
}

__device__ void proc_norm(const float4* __restrict__ pt, float4* __restrict__ out_proc,
                          int b, int sub) {
    wait_for(&g_cnt[b], PBLK);

    __shared__ float sm, sr;
    if (threadIdx.x < 32) {
        int lane = threadIdx.x;
        float s = 0.f, ss = 0.f, c = 0.f;
        if (lane < PBLK) {
            s  = g_part[b][lane][0];
            ss = g_part[b][lane][1];
            c  = g_part[b][lane][2];
        }
#pragma unroll
        for (int o = 8; o > 0; o >>= 1) {
            s  += __shfl_down_sync(0xffffffffu, s, o);
            ss += __shfl_down_sync(0xffffffffu, ss, o);
            c  += __shfl_down_sync(0xffffffffu, c, o);
        }
        if (lane == 0) {
            float m   = s / c;
            float var = (ss - s * s / c) / (c - 1.f);
            sm = m;
            sr = 1.f / (sqrtf(var) + EPSF);
        }
    }
    __syncthreads();
    retire(&g_fin[b], &g_cnt[b], NPB);
    const float m = sm, r = sr;

    const size_t base = (size_t)b * (S * NM / 4) + (size_t)sub * 2048;
    const float4* src = pt + base;
    float4*       dst = out_proc + base;
    for (int i0 = threadIdx.x; i0 < 2048; i0 += 512) {
        float4 v0 = __ldcs(&src[i0]);
        float4 v1 = __ldcs(&src[i0 + 256]);
        float4 o0, o1;
        o0.x = (v0.x != 0.f) ? (v0.x - m) * r : 0.f;
        o0.y = (v0.y != 0.f) ? (v0.y - m) * r : 0.f;
        o0.z = (v0.z != 0.f) ? (v0.z - m) * r : 0.f;
        o0.w = (v0.w != 0.f) ? (v0.w - m) * r : 0.f;
        o1.x = (v1.x != 0.f) ? (v1.x - m) * r : 0.f;
        o1.y = (v1.y != 0.f) ? (v1.y - m) * r : 0.f;
        o1.z = (v1.z != 0.f) ? (v1.z - m) * r : 0.f;
        o1.w = (v1.w != 0.f) ? (v1.w - m) * r : 0.f;
        __stcs(&dst[i0], o0);
        __stcs(&dst[i0 + 256], o1);
    }
}

__device__ void opes_norm(const float* __restrict__ opes, float4* __restrict__ out_opes,
                          const float* __restrict__ mas, float* __restrict__ out_mas,
                          const int* __restrict__ nums, int b, int sub) {
    const int base = b * 8192 + sub * 1024;

    wait_for(&g_ocnt[b], OSB);

    __shared__ float mm[FO], rr[FO];
    if (threadIdx.x < FO) {
        const int f = threadIdx.x;
        float ts = 0.f, tq = 0.f;
#pragma unroll
        for (int s2 = 0; s2 < OSB; s2++) {
            ts += g_opart[b][s2][0][f];
            tq += g_opart[b][s2][1][f];
        }
        float fn   = (float)nums[b];
        float mean = ts / fn;
        float var  = (tq - ts * ts / fn) / (fn - 1.f);
        mm[f] = mean;
        rr[f] = 1.f / (sqrtf(var) + EPSF);
    }
    __syncthreads();
    retire(&g_ofin[b], &g_ocnt[b], OPB);

    const float4* src = (const float4*)opes;
    for (int i0 = threadIdx.x; i0 < 1024; i0 += 512) {
        float4 v0 = __ldcs(&src[base + i0]);
        float4 v1 = __ldcs(&src[base + i0 + 256]);
        const float* M0 = &mm[(i0 & 1) * 4];
        const float* R0 = &rr[(i0 & 1) * 4];
        const float* M1 = &mm[((i0 + 256) & 1) * 4];
        const float* R1 = &rr[((i0 + 256) & 1) * 4];
        float4 o0, o1;
        o0.x = (v0.x - M0[0]) * R0[0];
        o0.y = (v0.y - M0[1]) * R0[1];
        o0.z = (v0.z - M0[2]) * R0[2];
        o0.w = (v0.w - M0[3]) * R0[3];
        o1.x = (v1.x - M1[0]) * R1[0];
        o1.y = (v1.y - M1[1]) * R1[1];
        o1.z = (v1.z - M1[2]) * R1[2];
        o1.w = (v1.w - M1[3]) * R1[3];
        __stcs(&out_opes[base + i0], o0);
        __stcs(&out_opes[base + i0 + 256], o1);
    }

    if (sub == 0) {
        const float* min_ = mas + (size_t)b * NM * FM;
        float*       mout = out_mas + (size_t)b * NM * FM;
        for (int i = threadIdx.x; i < NM * FM; i += 256) {
            int f = i % FM;
            mout[i] = (min_[i] - g_mmean[b * FM + f]) * g_mrstd[b * FM + f];
        }
    }
}

// ---------------- interleaved dispatch ----------------
__global__ void __launch_bounds__(256)
fusedAB_k(const float4* __restrict__ pt, float4* __restrict__ out_proc,
          const float* __restrict__ opes, float4* __restrict__ out_opes,
          const float* __restrict__ mas, float* __restrict__ out_mas,
          const int* __restrict__ nums) {
    const int bid = blockIdx.x;
    const int HEAD = LEAD * NSTAT;                              // 640
    const int MID  = HEAD + (NB - LEAD) * (NSTAT + NNORM);      // 640 + 13440 = 14080

    int b, sub, is_stats;
    if (bid < HEAD) {
        b = bid / NSTAT; sub = bid % NSTAT; is_stats = 1;
    } else if (bid < MID) {
        int t = bid - HEAD;
        int seg = t / (NSTAT + NNORM);
        int k   = t % (NSTAT + NNORM);
        if (k < NSTAT) { b = LEAD + seg; sub = k; is_stats = 1; }
        else           { b = seg;        sub = k - NSTAT; is_stats = 0; }
    } else {
        int t = bid - MID;
        b = (NB - LEAD) + t / NNORM; sub = t % NNORM; is_stats = 0;
    }

    if (is_stats) {
        if (sub < PBLK) proc_stats(pt, b, sub);
        else            opes_stats(opes, mas, nums, b, sub - PBLK);
    } else {
        if (sub < NPB)  proc_norm(pt, out_proc, b, sub);
        else            opes_norm(opes, out_opes, mas, out_mas, nums, b, sub - NPB);
    }
}

extern "C" void kernel_launch(void* const* d_in, const int* in_sizes, int n_in,
                              void* d_out, int out_size) {
    const float* raw_opes = (const float*)d_in[0];
    const float* raw_mas  = (const float*)d_in[1];
    const float* proc     = (const float*)d_in[2];
    const int*   nums     = (const int*)d_in[3];

    float* out_opes = (float*)d_out;
    float* out_mas  = out_opes + (size_t)NB * S * FO;
    float* out_proc = out_mas  + (size_t)NB * NM * FM;

    fusedAB_k<<<GRID_T, 256>>>((const float4*)proc, (float4*)out_proc,
                               raw_opes, (float4*)out_opes,
                               raw_mas, out_mas, nums);
}

// round 16
// speedup vs baseline: 1.8029x; 1.0558x over previous
#include <cuda_runtime.h>
#include <math.h>

#define NB 256
#define S  4096
#define FO 8
#define NM 64
#define FM 6
#define EPSF 1e-5f

#define PBLK 16     // proc stats sub-blocks per instance
#define OSB  4      // opes stats sub-blocks per instance
#define NPB  32     // proc norm sub-blocks per instance
#define OPB  8      // opes norm sub-blocks per instance
#define NSTAT (PBLK + OSB)     // 20
#define NNORM (NPB + OPB)      // 40
#define LEAD  32               // proven: full L2 reuse + minimal spin
#define GRID_T (NB * (NSTAT + NNORM))   // 15360

// -------- device scratch (fixed slots; flags self-reset each replay) --------
__device__ float g_part[NB][PBLK][4];
__device__ float g_opart[NB][OSB][2][FO];
__device__ float g_mmean[NB * FM];
__device__ float g_mrstd[NB * FM];
__device__ unsigned g_cnt[NB],  g_fin[NB];
__device__ unsigned g_ocnt[NB], g_ofin[NB];

__device__ __forceinline__ float warp_sum(float v) {
#pragma unroll
    for (int o = 16; o > 0; o >>= 1) v += __shfl_down_sync(0xffffffffu, v, o);
    return v;
}

__device__ __forceinline__ void wait_for(unsigned* cnt, unsigned target) {
    if (threadIdx.x == 0) {
        volatile unsigned* p = (volatile unsigned*)cnt;
        while (*p < target) __nanosleep(32);
        __threadfence();
    }
    __syncthreads();
}

__device__ __forceinline__ void retire(unsigned* fin, unsigned* cnt, unsigned nCons) {
    if (threadIdx.x == 0) {
        unsigned o = atomicAdd(fin, 1u);
        if (o == nCons - 1) { *cnt = 0u; *fin = 0u; }
    }
}

// ---------------- role bodies ----------------
__device__ void proc_stats(const float4* __restrict__ pt, int b, int sub) {
    const float4* src = pt + (size_t)b * (S * NM / 4) + (size_t)sub * 4096;
    float s = 0.f, ss = 0.f, c = 0.f;
    for (int i0 = threadIdx.x; i0 < 4096; i0 += 1024) {
        float4 v[4];
#pragma unroll
        for (int k = 0; k < 4; k++) v[k] = src[i0 + k * 256];   // cached: prime L2 for norm
#pragma unroll
        for (int k = 0; k < 4; k++) {
            s  += (v[k].x + v[k].y) + (v[k].z + v[k].w);
            ss += (v[k].x * v[k].x + v[k].y * v[k].y) + (v[k].z * v[k].z + v[k].w * v[k].w);
            c  += (float)((v[k].x != 0.f) + (v[k].y != 0.f) + (v[k].z != 0.f) + (v[k].w != 0.f));
        }
    }
    __shared__ float sh[3][8];
    int lane = threadIdx.x & 31, w = threadIdx.x >> 5;
    s = warp_sum(s); ss = warp_sum(ss); c = warp_sum(c);
    if (lane == 0) { sh[0][w] = s; sh[1][w] = ss; sh[2][w] = c; }
    __syncthreads();
    if (threadIdx.x == 0) {
        float ts = 0.f, tss = 0.f, tc = 0.f;
#pragma unroll
        for (int i = 0; i < 8; i++) { ts += sh[0][i]; tss += sh[1][i]; tc += sh[2][i]; }
        g_part[b][sub][0] = ts;
        g_part[b][sub][1] = tss;
        g_part[b][sub][2] = tc;
        __threadfence();
        atomicAdd(&g_cnt[b], 1u);
    }
}

__device__ void opes_stats(const float* __restrict__ opes, const float* __restrict__ mas,
                           const int* __restrict__ nums, int b, int sub) {
    const int n  = nums[b];
    const int r0 = sub * 1024;
    const int r1 = min(r0 + 1024, n);

    float s[FO], q[FO];
#pragma unroll
    for (int f = 0; f < FO; f++) { s[f] = 0.f; q[f] = 0.f; }

    const float4* op = (const float4*)(opes + (size_t)b * S * FO);
    for (int r = r0 + threadIdx.x; r < r1; r += 256) {
        float4 a  = op[r * 2];          // cached: prime L2 for norm
        float4 b4 = op[r * 2 + 1];
        float x[FO] = {a.x, a.y, a.z, a.w, b4.x, b4.y, b4.z, b4.w};
#pragma unroll
        for (int f = 0; f < FO; f++) { s[f] += x[f]; q[f] += x[f] * x[f]; }
    }
    __shared__ float sh[16][8];
    int lane = threadIdx.x & 31, w = threadIdx.x >> 5;
#pragma unroll
    for (int f = 0; f < FO; f++) {
        float rs = warp_sum(s[f]);
        float rq = warp_sum(q[f]);
        if (lane == 0) { sh[f][w] = rs; sh[f + 8][w] = rq; }
    }
    __syncthreads();
    if (threadIdx.x < FO) {
        int f = threadIdx.x;
        float ts = 0.f, tq = 0.f;
#pragma unroll
        for (int i = 0; i < 8; i++) { ts += sh[f][i]; tq += sh[f + 8][i]; }
        g_opart[b][sub][0][f] = ts;
        g_opart[b][sub][1][f] = tq;
    }
    if (sub == 0 && threadIdx.x >= 64 && threadIdx.x < 64 + FM) {
        int f = threadIdx.x - 64;
        const float* mp = mas + (size_t)b * NM * FM + f;
        float ts = 0.f, tq = 0.f;
#pragma unroll
        for (int m = 0; m < NM; m++) { float x = mp[m * FM]; ts += x; tq += x * x; }
        float fm   = (float)NM;
        float mean = ts / fm;
        float var  = (tq - ts * ts / fm) / (fm - 1.f);
        g_mmean[b * FM + f] = mean;
        g_mrstd[b * FM + f] = 1.f / (sqrtf(var) + EPSF);
    }
    __syncthreads();
    if (threadIdx.x == 0) { __threadfence(); atomicAdd(&g_ocnt[b], 1u); }
}

__device__ void proc_norm(const float4* __restrict__ pt, float4* __restrict__ out_proc,
                          int b, int sub) {
    wait_for(&g_cnt[b], PBLK);

    __shared__ float sm, sr;
    if (threadIdx.x < 32) {
        int lane = threadIdx.x;
        float s = 0.f, ss = 0.f, c = 0.f;
        if (lane < PBLK) {
            s  = g_part[b][lane][0];
            ss = g_part[b][lane][1];
            c  = g_part[b][lane][2];
        }
#pragma unroll
        for (int o = 8; o > 0; o >>= 1) {
            s  += __shfl_down_sync(0xffffffffu, s, o);
            ss += __shfl_down_sync(0xffffffffu, ss, o);
            c  += __shfl_down_sync(0xffffffffu, c, o);
        }
        if (lane == 0) {
            float m   = s / c;
            float var = (ss - s * s / c) / (c - 1.f);
            sm = m;
            sr = 1.f / (sqrtf(var) + EPSF);
        }
    }
    __syncthreads();
    retire(&g_fin[b], &g_cnt[b], NPB);
    const float m = sm, r = sr;

    const size_t base = (size_t)b * (S * NM / 4) + (size_t)sub * 2048;
    const float4* src = pt + base;
    float4*       dst = out_proc + base;
    // 2048 float4 / 256 threads = 8 loads per thread, front-batched 4-wide
    for (int i0 = threadIdx.x; i0 < 2048; i0 += 1024) {
        float4 v[4];
#pragma unroll
        for (int k = 0; k < 4; k++) v[k] = __ldcs(&src[i0 + k * 256]);
#pragma unroll
        for (int k = 0; k < 4; k++) {
            float4 o;
            o.x = (v[k].x != 0.f) ? (v[k].x - m) * r : 0.f;
            o.y = (v[k].y != 0.f) ? (v[k].y - m) * r : 0.f;
            o.z = (v[k].z != 0.f) ? (v[k].z - m) * r : 0.f;
            o.w = (v[k].w != 0.f) ? (v[k].w - m) * r : 0.f;
            __stcs(&dst[i0 + k * 256], o);
        }
    }
}

__device__ void opes_norm(const float* __restrict__ opes, float4* __restrict__ out_opes,
                          const float* __restrict__ mas, float* __restrict__ out_mas,
                          const int* __restrict__ nums, int b, int sub) {
    const int base = b * 8192 + sub * 1024;

    wait_for(&g_ocnt[b], OSB);

    __shared__ float mm[FO], rr[FO];
    if (threadIdx.x < FO) {
        const int f = threadIdx.x;
        float ts = 0.f, tq = 0.f;
#pragma unroll
        for (int s2 = 0; s2 < OSB; s2++) {
            ts += g_opart[b][s2][0][f];
            tq += g_opart[b][s2][1][f];
        }
        float fn   = (float)nums[b];
        float mean = ts / fn;
        float var  = (tq - ts * ts / fn) / (fn - 1.f);
        mm[f] = mean;
        rr[f] = 1.f / (sqrtf(var) + EPSF);
    }
    __syncthreads();
    retire(&g_ofin[b], &g_ocnt[b], OPB);

    const float4* src = (const float4*)opes;
    // 1024 float4 / 256 threads = 4 loads per thread, fully front-batched
    {
        const int t = threadIdx.x;
        float4 v[4];
#pragma unroll
        for (int k = 0; k < 4; k++) v[k] = __ldcs(&src[base + t + k * 256]);
        // parity of (t + k*256) == parity of t: feature half fixed per thread
        const float* M = &mm[(t & 1) * 4];
        const float* R = &rr[(t & 1) * 4];
#pragma unroll
        for (int k = 0; k < 4; k++) {
            float4 o;
            o.x = (v[k].x - M[0]) * R[0];
            o.y = (v[k].y - M[1]) * R[1];
            o.z = (v[k].z - M[2]) * R[2];
            o.w = (v[k].w - M[3]) * R[3];
            __stcs(&out_opes[base + t + k * 256], o);
        }
    }

    if (sub == 0) {
        const float* min_ = mas + (size_t)b * NM * FM;
        float*       mout = out_mas + (size_t)b * NM * FM;
        for (int i = threadIdx.x; i < NM * FM; i += 256) {
            int f = i % FM;
            mout[i] = (min_[i] - g_mmean[b * FM + f]) * g_mrstd[b * FM + f];
        }
    }
}

// ---------------- interleaved dispatch ----------------
__global__ void __launch_bounds__(256)
fusedAB_k(const float4* __restrict__ pt, float4* __restrict__ out_proc,
          const float* __restrict__ opes, float4* __restrict__ out_opes,
          const float* __restrict__ mas, float* __restrict__ out_mas,
          const int* __restrict__ nums) {
    const int bid = blockIdx.x;
    const int HEAD = LEAD * NSTAT;                              // 640
    const int MID  = HEAD + (NB - LEAD) * (NSTAT + NNORM);      // 14080

    int b, sub, is_stats;
    if (bid < HEAD) {
        b = bid / NSTAT; sub = bid % NSTAT; is_stats = 1;
    } else if (bid < MID) {
        int t = bid - HEAD;
        int seg = t / (NSTAT + NNORM);
        int k   = t % (NSTAT + NNORM);
        if (k < NSTAT) { b = LEAD + seg; sub = k; is_stats = 1; }
        else           { b = seg;        sub = k - NSTAT; is_stats = 0; }
    } else {
        int t = bid - MID;
        b = (NB - LEAD) + t / NNORM; sub = t % NNORM; is_stats = 0;
    }

    if (is_stats) {
        if (sub < PBLK) proc_stats(pt, b, sub);
        else            opes_stats(opes, mas, nums, b, sub - PBLK);
    } else {
        if (sub < NPB)  proc_norm(pt, out_proc, b, sub);
        else            opes_norm(opes, out_opes, mas, out_mas, nums, b, sub - NPB);
    }
}

extern "C" void kernel_launch(void* const* d_in, const int* in_sizes, int n_in,
                              void* d_out, int out_size) {
    const float* raw_opes = (const float*)d_in[0];
    const float* raw_mas  = (const float*)d_in[1];
    const float* proc     = (const float*)d_in[2];
    const int*   nums     = (const int*)d_in[3];

    float* out_opes = (float*)d_out;
    float* out_mas  = out_opes + (size_t)NB * S * FO;
    float* out_proc = out_mas  + (size_t)NB * NM * FM;

    fusedAB_k<<<GRID_T, 256>>>((const float4*)proc, (float4*)out_proc,
                               raw_opes, (float4*)out_opes,
                               raw_mas, out_mas, nums);
}